// round 1
// baseline (speedup 1.0000x reference)
#include <cuda_runtime.h>

// Gaussian 3D covariance: cov = (R*diag(exp(ls))) @ R^T per point.
// N=4M, 28 B in + 36 B out per point -> pure HBM-streaming kernel.

constexpr int TPB = 256;

__global__ __launch_bounds__(TPB) void cov_kernel(
    const float4* __restrict__ quat,   // [n] as float4 (w,x,y,z per ref: q[:,0]=w)
    const float*  __restrict__ ls,     // [n*3]
    float*        __restrict__ out,    // [n*9]
    int n)
{
    __shared__ float sbuf[TPB * 9];

    const int i = blockIdx.x * TPB + threadIdx.x;
    if (i < n) {
        const float4 q4 = quat[i];
        const float sx = __expf(ls[3 * i + 0]);
        const float sy = __expf(ls[3 * i + 1]);
        const float sz = __expf(ls[3 * i + 2]);

        const float d   = q4.x * q4.x + q4.y * q4.y + q4.z * q4.z + q4.w * q4.w;
        const float inv = rsqrtf(fmaxf(d, 1e-24f));  // norm ~ 1; guard against 0
        const float qw = q4.x * inv;
        const float qx = q4.y * inv;
        const float qy = q4.z * inv;
        const float qz = q4.w * inv;

        const float r00 = 1.f - 2.f * (qy * qy + qz * qz);
        const float r01 = 2.f * (qx * qy - qz * qw);
        const float r02 = 2.f * (qx * qz + qy * qw);
        const float r10 = 2.f * (qx * qy + qz * qw);
        const float r11 = 1.f - 2.f * (qx * qx + qz * qz);
        const float r12 = 2.f * (qy * qz - qx * qw);
        const float r20 = 2.f * (qx * qz - qy * qw);
        const float r21 = 2.f * (qy * qz + qx * qw);
        const float r22 = 1.f - 2.f * (qx * qx + qy * qy);

        // RS rows (scale applied along columns j)
        const float a0 = r00 * sx, a1 = r01 * sy, a2 = r02 * sz;
        const float b0 = r10 * sx, b1 = r11 * sy, b2 = r12 * sz;
        const float c0 = r20 * sx, c1 = r21 * sy, c2 = r22 * sz;

        float* p = &sbuf[threadIdx.x * 9];
        p[0] = a0 * r00 + a1 * r01 + a2 * r02;
        p[1] = a0 * r10 + a1 * r11 + a2 * r12;
        p[2] = a0 * r20 + a1 * r21 + a2 * r22;
        p[3] = b0 * r00 + b1 * r01 + b2 * r02;
        p[4] = b0 * r10 + b1 * r11 + b2 * r12;
        p[5] = b0 * r20 + b1 * r21 + b2 * r22;
        p[6] = c0 * r00 + c1 * r01 + c2 * r02;
        p[7] = c0 * r10 + c1 * r11 + c2 * r12;
        p[8] = c0 * r20 + c1 * r21 + c2 * r22;
    }
    __syncthreads();

    // Coalesced streaming store of this block's 9*blockPts floats.
    const int blockPts    = min(TPB, n - blockIdx.x * TPB);
    const int totalFloats = blockPts * 9;
    const long long base  = (long long)blockIdx.x * (TPB * 9);

    if ((totalFloats & 3) == 0) {
        // Full block path: 2304 floats = 576 float4s, base is 16B-aligned
        // (blockIdx * 9216 bytes).
        float4*       o4 = reinterpret_cast<float4*>(out + base);
        const float4* s4 = reinterpret_cast<const float4*>(sbuf);
        const int nvec = totalFloats >> 2;
        #pragma unroll
        for (int j = threadIdx.x; j < nvec; j += TPB)
            o4[j] = s4[j];
    } else {
        for (int j = threadIdx.x; j < totalFloats; j += TPB)
            out[base + j] = sbuf[j];
    }
}

extern "C" void kernel_launch(void* const* d_in, const int* in_sizes, int n_in,
                              void* d_out, int out_size) {
    const float4* quat = (const float4*)d_in[0];  // [N,4] float32
    const float*  ls   = (const float*)d_in[1];   // [N,3] float32
    float*        out  = (float*)d_out;           // [N,3,3] float32

    const int n = in_sizes[0] / 4;
    const int blocks = (n + TPB - 1) / TPB;
    cov_kernel<<<blocks, TPB>>>(quat, ls, out, n);
}

// round 2
// speedup vs baseline: 1.0116x; 1.0116x over previous
#include <cuda_runtime.h>

// Gaussian 3D covariance: cov = (R*diag(exp(ls))) @ R^T per point.
// N=4M, 28 B in + 36 B out per point -> pure HBM-streaming kernel.
// R2: 2 points/thread (MLP + ILP), streaming cache hints, smem-staged
// coalesced float4 output.

constexpr int TPB = 256;
constexpr int PPT = 2;                 // points per thread
constexpr int PPB = TPB * PPT;         // 512 points per block

__device__ __forceinline__ void compute_cov(const float4 q4,
                                            const float lsx, const float lsy, const float lsz,
                                            float* __restrict__ p) {
    const float sx = __expf(lsx);
    const float sy = __expf(lsy);
    const float sz = __expf(lsz);

    const float d   = q4.x * q4.x + q4.y * q4.y + q4.z * q4.z + q4.w * q4.w;
    const float inv = rsqrtf(fmaxf(d, 1e-24f));
    const float qw = q4.x * inv;
    const float qx = q4.y * inv;
    const float qy = q4.z * inv;
    const float qz = q4.w * inv;

    const float r00 = 1.f - 2.f * (qy * qy + qz * qz);
    const float r01 = 2.f * (qx * qy - qz * qw);
    const float r02 = 2.f * (qx * qz + qy * qw);
    const float r10 = 2.f * (qx * qy + qz * qw);
    const float r11 = 1.f - 2.f * (qx * qx + qz * qz);
    const float r12 = 2.f * (qy * qz - qx * qw);
    const float r20 = 2.f * (qx * qz - qy * qw);
    const float r21 = 2.f * (qy * qz + qx * qw);
    const float r22 = 1.f - 2.f * (qx * qx + qy * qy);

    const float a0 = r00 * sx, a1 = r01 * sy, a2 = r02 * sz;
    const float b0 = r10 * sx, b1 = r11 * sy, b2 = r12 * sz;
    const float c0 = r20 * sx, c1 = r21 * sy, c2 = r22 * sz;

    p[0] = a0 * r00 + a1 * r01 + a2 * r02;
    p[1] = a0 * r10 + a1 * r11 + a2 * r12;
    p[2] = a0 * r20 + a1 * r21 + a2 * r22;
    p[3] = b0 * r00 + b1 * r01 + b2 * r02;
    p[4] = b0 * r10 + b1 * r11 + b2 * r12;
    p[5] = b0 * r20 + b1 * r21 + b2 * r22;
    p[6] = c0 * r00 + c1 * r01 + c2 * r02;
    p[7] = c0 * r10 + c1 * r11 + c2 * r12;
    p[8] = c0 * r20 + c1 * r21 + c2 * r22;
}

__global__ __launch_bounds__(TPB) void cov_kernel(
    const float4* __restrict__ quat,   // [n] as float4 (w,x,y,z)
    const float*  __restrict__ ls,     // [n*3]
    float*        __restrict__ out,    // [n*9]
    int n)
{
    __shared__ float sbuf[PPB * 9];    // 18432 B

    const int base = blockIdx.x * PPB;
    const int i0 = base + threadIdx.x;         // point 0
    const int i1 = i0 + TPB;                   // point 1

    // Front-batch all global loads (maximize MLP).
    float4 q0, q1;
    float l00 = 0.f, l01 = 0.f, l02 = 0.f, l10 = 0.f, l11 = 0.f, l12 = 0.f;
    const bool v0 = i0 < n, v1 = i1 < n;
    if (v0) {
        q0  = __ldcs(&quat[i0]);
        l00 = __ldcs(&ls[3 * i0 + 0]);
        l01 = __ldcs(&ls[3 * i0 + 1]);
        l02 = __ldcs(&ls[3 * i0 + 2]);
    }
    if (v1) {
        q1  = __ldcs(&quat[i1]);
        l10 = __ldcs(&ls[3 * i1 + 0]);
        l11 = __ldcs(&ls[3 * i1 + 1]);
        l12 = __ldcs(&ls[3 * i1 + 2]);
    }

    if (v0) compute_cov(q0, l00, l01, l02, &sbuf[threadIdx.x * 9]);
    if (v1) compute_cov(q1, l10, l11, l12, &sbuf[(threadIdx.x + TPB) * 9]);
    __syncthreads();

    // Coalesced streaming store of this block's 9*blockPts floats.
    const int blockPts    = min(PPB, n - base);
    const int totalFloats = blockPts * 9;
    const long long obase = (long long)base * 9;

    if ((totalFloats & 3) == 0) {
        // Full-block path: 4608 floats = 1152 float4s; obase*4 is 16B-aligned
        // (base multiple of 512 -> obase multiple of 4608, *4B = 18432B).
        float4*       o4 = reinterpret_cast<float4*>(out + obase);
        const float4* s4 = reinterpret_cast<const float4*>(sbuf);
        const int nvec = totalFloats >> 2;
        #pragma unroll
        for (int j = threadIdx.x; j < nvec; j += TPB)
            __stcs(&o4[j], s4[j]);
    } else {
        for (int j = threadIdx.x; j < totalFloats; j += TPB)
            out[obase + j] = sbuf[j];
    }
}

extern "C" void kernel_launch(void* const* d_in, const int* in_sizes, int n_in,
                              void* d_out, int out_size) {
    const float4* quat = (const float4*)d_in[0];  // [N,4] float32
    const float*  ls   = (const float*)d_in[1];   // [N,3] float32
    float*        out  = (float*)d_out;           // [N,3,3] float32

    const int n = in_sizes[0] / 4;
    const int blocks = (n + PPB - 1) / PPB;
    cov_kernel<<<blocks, TPB>>>(quat, ls, out, n);
}